// round 12
// baseline (speedup 1.0000x reference)
#include <cuda_runtime.h>
#include <cuda_fp16.h>
#include <stdint.h>

#define NN 65536
#define DD 256
#define KK 4096
#define BM 32
#define BN 128
#define FCAP 65536
#define M2 1.25f

__device__ float g_acc[KK * DD];
__device__ float g_cntf[KK];
__device__ float g_c2[KK];
__device__ unsigned g_cbt[128 * KK];       // f16x2 centers, k2-major: [k2][n]
__device__ float g_loss;
__device__ int g_flagcnt;
__device__ int g_flagrows[FCAP];
__device__ int g_candn[FCAP];
__device__ unsigned g_cand[(size_t)FCAP * 32];

__device__ __forceinline__ unsigned pack_h2(float lo, float hi) {
    __half2 h = __floats2half2_rn(lo, hi);
    return *reinterpret_cast<unsigned*>(&h);
}
__device__ __forceinline__ float2 unpack_h2(unsigned u) {
    __half2 h = *reinterpret_cast<__half2*>(&u);
    return __half22float2(h);
}

#define MMA16H(d, a, b0, b1)                                                   \
    asm volatile("mma.sync.aligned.m16n8k16.row.col.f16.f16.f16.f16 "         \
        "{%0,%1}, {%2,%3,%4,%5}, {%6,%7}, {%0,%1};"                           \
        : "+r"((d)[0]), "+r"((d)[1])                                          \
        : "r"((a).x), "r"((a).y), "r"((a).z), "r"((a).w), "r"(b0), "r"(b1))

// ------------------------------- init -------------------------------
__global__ void init_kernel(const float* __restrict__ centers,
                            const int* __restrict__ counts) {
    int k = blockIdx.x, d = threadIdx.x;
    __shared__ float cs[DD];
    float c = centers[(size_t)k * DD + d];
    float cnt = (float)counts[k];
    g_acc[(size_t)k * DD + d] = cnt * c;
    cs[d] = c;
    __shared__ float red[8];
    float v = c * c;
    #pragma unroll
    for (int o = 16; o > 0; o >>= 1) v += __shfl_down_sync(~0u, v, o);
    if ((d & 31) == 0) red[d >> 5] = v;
    __syncthreads();
    if (d < 128)
        g_cbt[(size_t)d * KK + k] = pack_h2(cs[2 * d], cs[2 * d + 1]);
    if (d == 0) {
        float s = 0.f;
        #pragma unroll
        for (int w = 0; w < 8; ++w) s += red[w];
        g_c2[k] = s; g_cntf[k] = cnt;
        if (k == 0) { g_loss = 0.f; g_flagcnt = 0; }
    }
}

// --- f16 mma GEMM (BM=32) + top-2 argmin + fused scatter, occ 3 ---
#define B_OFF 4096
#define BBUF 2176
#define SMEM_U32 (B_OFF + 2 * BBUF)
#define GEMM_SMEM (SMEM_U32 * 4)

__global__ void __launch_bounds__(256, 3)
gemm_kernel(const float* __restrict__ emb, const float* __restrict__ centers,
            float* __restrict__ labels_out) {
    extern __shared__ unsigned smu[];
    const int tid = threadIdx.x, lane = tid & 31, wid = tid >> 5;
    const int warp_m = wid >> 2, warp_n = wid & 3;   // 2 x 4 warp grid
    const int g = lane >> 2, t = lane & 3;
    const int row0 = blockIdx.x * BM;

    // ---- stage A: f16 fragment-major, 32 rows ----
    #pragma unroll 4
    for (int it = 0; it < 8; ++it) {
        int i = it * 256 + tid;
        int m = i >> 6, kq = i & 63;
        float4 v = *reinterpret_cast<const float4*>(emb + (size_t)(row0 + m) * DD + kq * 4);
        unsigned w0 = pack_h2(v.x, v.y), w1 = pack_h2(v.z, v.w);
        int rr = m & 15, mt = m >> 4;
        #pragma unroll
        for (int hh = 0; hh < 2; ++hh) {
            int k2 = 2 * kq + hh;
            int sg = k2 >> 3, kw = k2 & 7;
            int L = (rr & 7) * 4 + (kw & 3);
            int j = (rr >> 3) + 2 * (kw >> 2);
            smu[((sg * 2 + mt) * 32 + L) * 4 + j] = hh ? w1 : w0;
        }
    }

    float sv1[2], sv2[2]; int si1[2], si2[2];
    #pragma unroll
    for (int s = 0; s < 2; ++s) { sv1[s] = sv2[s] = 3.4e38f; si1[s] = si2[s] = 0; }
    __syncthreads();

    const int pk2r = tid >> 4, pn8 = (tid & 15) * 8;

    #pragma unroll 1
    for (int tile = 0; tile < KK / BN; ++tile) {
        const int j0 = tile * BN;
        unsigned acc[4][2];
        #pragma unroll
        for (int b = 0; b < 4; ++b) { acc[b][0] = 0u; acc[b][1] = 0u; }

        uint4 p0, p1;
        {
            const uint4* src = reinterpret_cast<const uint4*>(
                g_cbt + (size_t)pk2r * KK + j0 + pn8);
            p0 = src[0]; p1 = src[1];
            uint4* dst = reinterpret_cast<uint4*>(smu + B_OFF + pk2r * 136 + pn8);
            dst[0] = p0; dst[1] = p1;
        }
        __syncthreads();

        #pragma unroll 1
        for (int ch = 0; ch < 8; ++ch) {
            const int buf = ch & 1;
            if (ch < 7) {
                const uint4* src = reinterpret_cast<const uint4*>(
                    g_cbt + (size_t)((ch + 1) * 16 + pk2r) * KK + j0 + pn8);
                p0 = src[0]; p1 = src[1];
            }
            const unsigned* Bb = smu + B_OFF + buf * BBUF;
            #pragma unroll
            for (int s4 = 0; s4 < 2; ++s4) {
                const int sg = ch * 2 + s4;
                uint4 a = *(reinterpret_cast<const uint4*>(smu) +
                            ((sg * 2 + warp_m) * 32 + lane));
                unsigned bb[4][2];
                #pragma unroll
                for (int nt = 0; nt < 4; ++nt) {
                    int col = warp_n * 32 + nt * 8 + g;
                    bb[nt][0] = Bb[(s4 * 8 + t) * 136 + col];
                    bb[nt][1] = Bb[(s4 * 8 + t + 4) * 136 + col];
                }
                #pragma unroll
                for (int nt = 0; nt < 4; ++nt)
                    MMA16H(acc[nt], a, bb[nt][0], bb[nt][1]);
            }
            if (ch < 7) {
                uint4* dst = reinterpret_cast<uint4*>(
                    smu + B_OFF + (buf ^ 1) * BBUF + pk2r * 136 + pn8);
                dst[0] = p0; dst[1] = p1;
            }
            __syncthreads();
        }

        // per-tile epilogue: v = c2 - 2*dot, top-2 insert per row-slot
        #pragma unroll
        for (int nt = 0; nt < 4; ++nt) {
            const int cb = j0 + warp_n * 32 + nt * 8 + 2 * t;
            const float c20 = __ldg(&g_c2[cb]);
            const float c21 = __ldg(&g_c2[cb + 1]);
            #pragma unroll
            for (int h = 0; h < 2; ++h) {
                float2 f = unpack_h2(acc[nt][h]);
                #pragma unroll
                for (int e = 0; e < 2; ++e) {
                    float v = fmaf(-2.f, e ? f.y : f.x, e ? c21 : c20);
                    int c = cb + e;
                    if (v < sv2[h]) {
                        if (v < sv1[h]) {
                            sv2[h] = sv1[h]; si2[h] = si1[h];
                            sv1[h] = v; si1[h] = c;
                        } else { sv2[h] = v; si2[h] = c; }
                    }
                }
            }
        }
    }

    // ---- merge: alias reduction arrays over A smem region ----
    __syncthreads();
    float* V1 = (float*)smu;            // [16][32]
    float* V2 = V1 + 512;
    int*   I1 = (int*)(V2 + 512);
    int*   I2 = I1 + 512;
    int*   labs = I2 + 512;             // [32]
    float* lred = (float*)(labs + 32);  // [8]
    const int slot = warp_n * 4 + t;
    #pragma unroll
    for (int s = 0; s < 2; ++s) {
        int row = warp_m * 16 + s * 8 + g;
        V1[slot * 32 + row] = sv1[s]; I1[slot * 32 + row] = si1[s];
        V2[slot * 32 + row] = sv2[s]; I2[slot * 32 + row] = si2[s];
    }
    __syncthreads();

    if (tid < 32) {
        float v1 = 3.4e38f, v2 = 3.4e38f; int i1 = 1 << 30;
        #pragma unroll
        for (int s = 0; s < 16; ++s) {
            float a1 = V1[s * 32 + tid], a2 = V2[s * 32 + tid];
            int   b1 = I1[s * 32 + tid];
            bool lt = (a1 < v1) || (a1 == v1 && b1 < i1);
            if (lt) { v2 = v1; v1 = a1; i1 = b1; } else if (a1 < v2) v2 = a1;
            if (a2 < v2) v2 = a2;
        }
        labels_out[row0 + tid] = (float)i1;
        labs[tid] = i1;
        if (v2 - v1 < M2) {
            int p = atomicAdd(&g_flagcnt, 1);
            g_flagrows[p] = row0 + tid;
            const float thr = v1 + M2;
            int nc = 0;
            #pragma unroll
            for (int s = 0; s < 16; ++s) {
                if (V1[s * 32 + tid] < thr)
                    g_cand[(size_t)p * 32 + nc++] = (unsigned)I1[s * 32 + tid];
                if (V2[s * 32 + tid] < thr)
                    g_cand[(size_t)p * 32 + nc++] = (unsigned)I2[s * 32 + tid];
            }
            g_candn[p] = nc;
        }
    }
    __syncthreads();

    // ---- fused scatter: exact loss + segment sums + counts ----
    float lsum = 0.f;
    #pragma unroll 1
    for (int r = 0; r < BM; ++r) {
        const int lab = labs[r];
        float x = emb[(size_t)(row0 + r) * DD + tid];
        float c = __ldg(&centers[(size_t)lab * DD + tid]);
        float d = x - c;
        lsum = fmaf(d, d, lsum);
        atomicAdd(&g_acc[(size_t)lab * DD + tid], x);
        if (tid == 0) atomicAdd(&g_cntf[lab], 1.0f);
    }
    #pragma unroll
    for (int o = 16; o > 0; o >>= 1) lsum += __shfl_down_sync(~0u, lsum, o);
    if (lane == 0) lred[wid] = lsum;
    __syncthreads();
    if (tid == 0) {
        float s = 0.f;
        #pragma unroll
        for (int w = 0; w < 8; ++w) s += lred[w];
        atomicAdd(&g_loss, s);
    }
}

// ---- exact fp32 rescore over filtered candidates + inline fix ----
__global__ void __launch_bounds__(256)
rescore_kernel(const float* __restrict__ emb, const float* __restrict__ centers,
               float* __restrict__ labels_out) {
    const int lane = threadIdx.x & 31, w = threadIdx.x >> 5;
    const int cnt = g_flagcnt;
    for (int fi = blockIdx.x * 8 + w; fi < cnt; fi += gridDim.x * 8) {
        const int row = g_flagrows[fi];
        const int nc = g_candn[fi];
        const float4* xp = reinterpret_cast<const float4*>(emb + (size_t)row * DD);
        float4 x0 = __ldg(xp + 2 * lane);
        float4 x1 = __ldg(xp + 2 * lane + 1);
        float best = 3.4e38f; int bi = 1 << 30;
        #pragma unroll 1
        for (int q = 0; q < nc; ++q) {
            int c = (int)g_cand[(size_t)fi * 32 + q];
            const float4* cp = reinterpret_cast<const float4*>(centers + (size_t)c * DD);
            float4 c0 = __ldg(cp + 2 * lane);
            float4 c1 = __ldg(cp + 2 * lane + 1);
            float dot = x0.x * c0.x;
            dot = fmaf(x0.y, c0.y, dot); dot = fmaf(x0.z, c0.z, dot);
            dot = fmaf(x0.w, c0.w, dot); dot = fmaf(x1.x, c1.x, dot);
            dot = fmaf(x1.y, c1.y, dot); dot = fmaf(x1.z, c1.z, dot);
            dot = fmaf(x1.w, c1.w, dot);
            #pragma unroll
            for (int o = 16; o > 0; o >>= 1) dot += __shfl_xor_sync(~0u, dot, o);
            float v = fmaf(-2.f, dot, __ldg(&g_c2[c]));
            if (v < best || (v == best && c < bi)) { best = v; bi = c; }
        }
        const int old = (int)__shfl_sync(~0u, labels_out[row], 0);  // uniform read
        bi = __shfl_sync(~0u, bi, 0);
        if (bi != old) {
            if (lane == 0) labels_out[row] = (float)bi;
            // inline fix: move row between centers, patch loss/counts (exact)
            float ls = 0.f;
            #pragma unroll
            for (int u = 0; u < 8; ++u) {
                int col = lane * 8 + u;
                float x = (u < 4) ? (&x0.x)[u] : (&x1.x)[u - 4];
                float co = __ldg(&centers[(size_t)old * DD + col]);
                float cn = __ldg(&centers[(size_t)bi * DD + col]);
                atomicAdd(&g_acc[(size_t)old * DD + col], -x);
                atomicAdd(&g_acc[(size_t)bi * DD + col], x);
                float dn = x - cn, dd = x - co;
                ls += dn * dn - dd * dd;
            }
            #pragma unroll
            for (int o = 16; o > 0; o >>= 1) ls += __shfl_xor_sync(~0u, ls, o);
            if (lane == 0) {
                atomicAdd(&g_loss, ls);
                atomicAdd(&g_cntf[old], -1.0f);
                atomicAdd(&g_cntf[bi], 1.0f);
            }
        }
    }
}

__global__ void finalize_kernel(float* __restrict__ out) {
    int k = blockIdx.x, d = threadIdx.x;
    float cnt = g_cntf[k];
    out[(size_t)NN + (size_t)k * DD + d] = g_acc[(size_t)k * DD + d] / cnt;
    if (d == 0) out[(size_t)NN + (size_t)KK * DD + k] = cnt;
    if (k == 0 && d == 0) out[(size_t)NN + (size_t)KK * DD + KK] = g_loss / (float)NN;
}

extern "C" void kernel_launch(void* const* d_in, const int* in_sizes, int n_in,
                              void* d_out, int out_size) {
    const float* emb     = (const float*)d_in[0];
    const float* centers = (const float*)d_in[1];
    const int*   counts  = (const int*)d_in[2];
    float* out = (float*)d_out;

    cudaFuncSetAttribute(gemm_kernel, cudaFuncAttributeMaxDynamicSharedMemorySize, GEMM_SMEM);

    init_kernel<<<KK, 256>>>(centers, counts);
    gemm_kernel<<<NN / BM, 256, GEMM_SMEM>>>(emb, centers, out);
    rescore_kernel<<<1024, 256>>>(emb, centers, out);
    finalize_kernel<<<KK, DD>>>(out);
}

// round 13
// speedup vs baseline: 1.7966x; 1.7966x over previous
#include <cuda_runtime.h>
#include <cuda_fp16.h>
#include <stdint.h>

#define NN 65536
#define DD 256
#define KK 4096
#define BM 128
#define BN 128
#define FCAP 65536
#define M2 1.25f

__device__ float g_acc[KK * DD];
__device__ float g_cntf[KK];
__device__ float g_c2[KK];
__device__ unsigned g_cbt[128 * KK];       // f16x2 centers, k2-major: [k2][n]
__device__ float g_loss;
__device__ int g_flagcnt;
__device__ int g_flagrows[FCAP];
__device__ int g_candn[FCAP];
__device__ unsigned g_cand[(size_t)FCAP * 32];

__device__ __forceinline__ unsigned pack_h2(float lo, float hi) {
    __half2 h = __floats2half2_rn(lo, hi);
    return *reinterpret_cast<unsigned*>(&h);
}
__device__ __forceinline__ float2 unpack_h2(unsigned u) {
    __half2 h = *reinterpret_cast<__half2*>(&u);
    return __half22float2(h);
}

#define MMA16H(d, a, b0, b1)                                                   \
    asm volatile("mma.sync.aligned.m16n8k16.row.col.f16.f16.f16.f16 "         \
        "{%0,%1}, {%2,%3,%4,%5}, {%6,%7}, {%0,%1};"                           \
        : "+r"((d)[0]), "+r"((d)[1])                                          \
        : "r"((a).x), "r"((a).y), "r"((a).z), "r"((a).w), "r"(b0), "r"(b1))

// ------------------------------- init -------------------------------
__global__ void init_kernel(const float* __restrict__ centers,
                            const int* __restrict__ counts) {
    int k = blockIdx.x, d = threadIdx.x;
    __shared__ float cs[DD];
    float c = centers[(size_t)k * DD + d];
    float cnt = (float)counts[k];
    g_acc[(size_t)k * DD + d] = cnt * c;
    cs[d] = c;
    __shared__ float red[8];
    float v = c * c;
    #pragma unroll
    for (int o = 16; o > 0; o >>= 1) v += __shfl_down_sync(~0u, v, o);
    if ((d & 31) == 0) red[d >> 5] = v;
    __syncthreads();
    if (d < 128)
        g_cbt[(size_t)d * KK + k] = pack_h2(cs[2 * d], cs[2 * d + 1]);
    if (d == 0) {
        float s = 0.f;
        #pragma unroll
        for (int w = 0; w < 8; ++w) s += red[w];
        g_c2[k] = s; g_cntf[k] = cnt;
        if (k == 0) { g_loss = 0.f; g_flagcnt = 0; }
    }
}

// --- f16 mma GEMM (BM=128, f16 accum) + top-2 argmin + fused scatter, occ 2 ---
#define B_OFF 16384
#define BBUF 2176
#define SMEM_U32 (B_OFF + 2 * BBUF)
#define GEMM_SMEM (SMEM_U32 * 4)

__global__ void __launch_bounds__(256, 2)
gemm_kernel(const float* __restrict__ emb, const float* __restrict__ centers,
            float* __restrict__ labels_out) {
    extern __shared__ unsigned smu[];
    const int tid = threadIdx.x, lane = tid & 31, wid = tid >> 5;
    const int warp_m = wid >> 2, warp_n = wid & 3;   // 2 x 4 warp grid
    const int g = lane >> 2, t = lane & 3;
    const int row0 = blockIdx.x * BM;

    // ---- stage A: f16 fragment-major, 128 rows ----
    #pragma unroll 4
    for (int it = 0; it < 32; ++it) {
        int i = it * 256 + tid;
        int m = i >> 6, kq = i & 63;
        float4 v = *reinterpret_cast<const float4*>(emb + (size_t)(row0 + m) * DD + kq * 4);
        unsigned w0 = pack_h2(v.x, v.y), w1 = pack_h2(v.z, v.w);
        int rr = m & 15, mt = m >> 4;
        #pragma unroll
        for (int hh = 0; hh < 2; ++hh) {
            int k2 = 2 * kq + hh;
            int sg = k2 >> 3, kw = k2 & 7;
            int L = (rr & 7) * 4 + (kw & 3);
            int j = (rr >> 3) + 2 * (kw >> 2);
            smu[((sg * 8 + mt) * 32 + L) * 4 + j] = hh ? w1 : w0;
        }
    }

    float sv1[8], sv2[8]; int si1[8], si2[8];
    #pragma unroll
    for (int s = 0; s < 8; ++s) { sv1[s] = sv2[s] = 3.4e38f; si1[s] = si2[s] = 0; }
    __syncthreads();

    const int pk2r = tid >> 4, pn8 = (tid & 15) * 8;

    #pragma unroll 1
    for (int tile = 0; tile < KK / BN; ++tile) {
        const int j0 = tile * BN;
        unsigned acc[4][4][2];
        #pragma unroll
        for (int a = 0; a < 4; ++a)
            #pragma unroll
            for (int b = 0; b < 4; ++b) { acc[a][b][0] = 0u; acc[a][b][1] = 0u; }

        uint4 p0, p1;
        {
            const uint4* src = reinterpret_cast<const uint4*>(
                g_cbt + (size_t)pk2r * KK + j0 + pn8);
            p0 = src[0]; p1 = src[1];
            uint4* dst = reinterpret_cast<uint4*>(smu + B_OFF + pk2r * 136 + pn8);
            dst[0] = p0; dst[1] = p1;
        }
        __syncthreads();

        #pragma unroll 1
        for (int ch = 0; ch < 8; ++ch) {
            const int buf = ch & 1;
            if (ch < 7) {
                const uint4* src = reinterpret_cast<const uint4*>(
                    g_cbt + (size_t)((ch + 1) * 16 + pk2r) * KK + j0 + pn8);
                p0 = src[0]; p1 = src[1];
            }
            const unsigned* Bb = smu + B_OFF + buf * BBUF;
            #pragma unroll
            for (int s4 = 0; s4 < 2; ++s4) {
                const int sg = ch * 2 + s4;
                uint4 a[4];
                #pragma unroll
                for (int mi = 0; mi < 4; ++mi)
                    a[mi] = *(reinterpret_cast<const uint4*>(smu) +
                              ((sg * 8 + warp_m * 4 + mi) * 32 + lane));
                unsigned bb[4][2];
                #pragma unroll
                for (int nt = 0; nt < 4; ++nt) {
                    int col = warp_n * 32 + nt * 8 + g;
                    bb[nt][0] = Bb[(s4 * 8 + t) * 136 + col];
                    bb[nt][1] = Bb[(s4 * 8 + t + 4) * 136 + col];
                }
                #pragma unroll
                for (int mi = 0; mi < 4; ++mi)
                    #pragma unroll
                    for (int nt = 0; nt < 4; ++nt)
                        MMA16H(acc[mi][nt], a[mi], bb[nt][0], bb[nt][1]);
            }
            if (ch < 7) {
                uint4* dst = reinterpret_cast<uint4*>(
                    smu + B_OFF + (buf ^ 1) * BBUF + pk2r * 136 + pn8);
                dst[0] = p0; dst[1] = p1;
            }
            __syncthreads();
        }

        // per-tile epilogue: v = c2 - 2*dot, top-2 insert per row-slot
        #pragma unroll
        for (int nt = 0; nt < 4; ++nt) {
            const int cb = j0 + warp_n * 32 + nt * 8 + 2 * t;
            const float c20 = __ldg(&g_c2[cb]);
            const float c21 = __ldg(&g_c2[cb + 1]);
            #pragma unroll
            for (int mi = 0; mi < 4; ++mi) {
                #pragma unroll
                for (int h = 0; h < 2; ++h) {
                    const int s = mi * 2 + h;
                    float2 f = unpack_h2(acc[mi][nt][h]);
                    #pragma unroll
                    for (int e = 0; e < 2; ++e) {
                        float v = fmaf(-2.f, e ? f.y : f.x, e ? c21 : c20);
                        int c = cb + e;
                        if (v < sv2[s]) {
                            if (v < sv1[s]) {
                                sv2[s] = sv1[s]; si2[s] = si1[s];
                                sv1[s] = v; si1[s] = c;
                            } else { sv2[s] = v; si2[s] = c; }
                        }
                    }
                }
            }
        }
    }

    // ---- merge: alias reduction arrays over A smem region ----
    __syncthreads();
    float* V1 = (float*)smu;            // [16][128]
    float* V2 = V1 + 2048;
    int*   I1 = (int*)(V2 + 2048);
    int*   I2 = I1 + 2048;
    int*   labs = I2 + 2048;            // [128]
    float* lred = (float*)(labs + 128); // [8]
    const int slot = warp_n * 4 + t;
    #pragma unroll
    for (int s = 0; s < 8; ++s) {
        int row = warp_m * 64 + (s >> 1) * 16 + (s & 1) * 8 + g;
        V1[slot * 128 + row] = sv1[s]; I1[slot * 128 + row] = si1[s];
        V2[slot * 128 + row] = sv2[s]; I2[slot * 128 + row] = si2[s];
    }
    __syncthreads();

    if (tid < 128) {
        float v1 = 3.4e38f, v2 = 3.4e38f; int i1 = 1 << 30;
        #pragma unroll
        for (int s = 0; s < 16; ++s) {
            float a1 = V1[s * 128 + tid], a2 = V2[s * 128 + tid];
            int   b1 = I1[s * 128 + tid];
            bool lt = (a1 < v1) || (a1 == v1 && b1 < i1);
            if (lt) { v2 = v1; v1 = a1; i1 = b1; } else if (a1 < v2) v2 = a1;
            if (a2 < v2) v2 = a2;
        }
        labels_out[row0 + tid] = (float)i1;
        labs[tid] = i1;
        if (v2 - v1 < M2) {
            int p = atomicAdd(&g_flagcnt, 1);
            g_flagrows[p] = row0 + tid;
            const float thr = v1 + M2;
            int nc = 0;
            #pragma unroll
            for (int s = 0; s < 16; ++s) {
                if (V1[s * 128 + tid] < thr)
                    g_cand[(size_t)p * 32 + nc++] = (unsigned)I1[s * 128 + tid];
                if (V2[s * 128 + tid] < thr)
                    g_cand[(size_t)p * 32 + nc++] = (unsigned)I2[s * 128 + tid];
            }
            g_candn[p] = nc;
        }
    }
    __syncthreads();

    // ---- fused scatter: exact loss + segment sums + counts ----
    float lsum = 0.f;
    #pragma unroll 1
    for (int r = 0; r < BM; ++r) {
        const int lab = labs[r];
        float x = emb[(size_t)(row0 + r) * DD + tid];
        float c = __ldg(&centers[(size_t)lab * DD + tid]);
        float d = x - c;
        lsum = fmaf(d, d, lsum);
        atomicAdd(&g_acc[(size_t)lab * DD + tid], x);
        if (tid == 0) atomicAdd(&g_cntf[lab], 1.0f);
    }
    #pragma unroll
    for (int o = 16; o > 0; o >>= 1) lsum += __shfl_down_sync(~0u, lsum, o);
    if (lane == 0) lred[wid] = lsum;
    __syncthreads();
    if (tid == 0) {
        float s = 0.f;
        #pragma unroll
        for (int w = 0; w < 8; ++w) s += lred[w];
        atomicAdd(&g_loss, s);
    }
}

// ---- exact fp32 rescore over filtered candidates + inline fix ----
__global__ void __launch_bounds__(256)
rescore_kernel(const float* __restrict__ emb, const float* __restrict__ centers,
               float* __restrict__ labels_out) {
    const int lane = threadIdx.x & 31, w = threadIdx.x >> 5;
    const int cnt = g_flagcnt;
    for (int fi = blockIdx.x * 8 + w; fi < cnt; fi += gridDim.x * 8) {
        const int row = g_flagrows[fi];
        const int nc = g_candn[fi];
        const float4* xp = reinterpret_cast<const float4*>(emb + (size_t)row * DD);
        float4 x0 = __ldg(xp + 2 * lane);
        float4 x1 = __ldg(xp + 2 * lane + 1);
        float best = 3.4e38f; int bi = 1 << 30;
        #pragma unroll 1
        for (int q = 0; q < nc; ++q) {
            int c = (int)g_cand[(size_t)fi * 32 + q];
            const float4* cp = reinterpret_cast<const float4*>(centers + (size_t)c * DD);
            float4 c0 = __ldg(cp + 2 * lane);
            float4 c1 = __ldg(cp + 2 * lane + 1);
            float dot = x0.x * c0.x;
            dot = fmaf(x0.y, c0.y, dot); dot = fmaf(x0.z, c0.z, dot);
            dot = fmaf(x0.w, c0.w, dot); dot = fmaf(x1.x, c1.x, dot);
            dot = fmaf(x1.y, c1.y, dot); dot = fmaf(x1.z, c1.z, dot);
            dot = fmaf(x1.w, c1.w, dot);
            #pragma unroll
            for (int o = 16; o > 0; o >>= 1) dot += __shfl_xor_sync(~0u, dot, o);
            float v = fmaf(-2.f, dot, __ldg(&g_c2[c]));
            if (v < best || (v == best && c < bi)) { best = v; bi = c; }
        }
        const int old = (int)__shfl_sync(~0u, labels_out[row], 0);
        bi = __shfl_sync(~0u, bi, 0);
        if (bi != old) {
            if (lane == 0) labels_out[row] = (float)bi;
            float ls = 0.f;
            #pragma unroll
            for (int u = 0; u < 8; ++u) {
                int col = lane * 8 + u;
                float x = (u < 4) ? (&x0.x)[u] : (&x1.x)[u - 4];
                float co = __ldg(&centers[(size_t)old * DD + col]);
                float cn = __ldg(&centers[(size_t)bi * DD + col]);
                atomicAdd(&g_acc[(size_t)old * DD + col], -x);
                atomicAdd(&g_acc[(size_t)bi * DD + col], x);
                float dn = x - cn, dd = x - co;
                ls += dn * dn - dd * dd;
            }
            #pragma unroll
            for (int o = 16; o > 0; o >>= 1) ls += __shfl_xor_sync(~0u, ls, o);
            if (lane == 0) {
                atomicAdd(&g_loss, ls);
                atomicAdd(&g_cntf[old], -1.0f);
                atomicAdd(&g_cntf[bi], 1.0f);
            }
        }
    }
}

__global__ void finalize_kernel(float* __restrict__ out) {
    int k = blockIdx.x, d = threadIdx.x;
    float cnt = g_cntf[k];
    out[(size_t)NN + (size_t)k * DD + d] = g_acc[(size_t)k * DD + d] / cnt;
    if (d == 0) out[(size_t)NN + (size_t)KK * DD + k] = cnt;
    if (k == 0 && d == 0) out[(size_t)NN + (size_t)KK * DD + KK] = g_loss / (float)NN;
}

extern "C" void kernel_launch(void* const* d_in, const int* in_sizes, int n_in,
                              void* d_out, int out_size) {
    const float* emb     = (const float*)d_in[0];
    const float* centers = (const float*)d_in[1];
    const int*   counts  = (const int*)d_in[2];
    float* out = (float*)d_out;

    cudaFuncSetAttribute(gemm_kernel, cudaFuncAttributeMaxDynamicSharedMemorySize, GEMM_SMEM);

    init_kernel<<<KK, 256>>>(centers, counts);
    gemm_kernel<<<NN / BM, 256, GEMM_SMEM>>>(emb, centers, out);
    rescore_kernel<<<1024, 256>>>(emb, centers, out);
    finalize_kernel<<<KK, DD>>>(out);
}